// round 3
// baseline (speedup 1.0000x reference)
#include <cuda_runtime.h>

// TypeAttention reduces algebraically to alpha[e] = 1 / in_degree(dst[e]) per
// relation (all edges into a dst share one logit -> uniform softmax).
// Single persistent kernel: histogram -> grid barrier -> per-node reciprocal
// -> grid barrier -> per-edge gather. One memset node zeros counts + barrier.

#define MAX_NODES 100000
#define TPB 256

// [0, MAX_NODES): cnt_ui   [MAX_NODES, 2*MAX_NODES): cnt_iu
// [2*MAX_NODES]: barrier counter. All zeroed by one memset per launch.
__device__ int   g_state[2 * MAX_NODES + 32];
__device__ float g_rcp[2 * MAX_NODES];   // fully overwritten, no zeroing

__device__ __forceinline__ void grid_barrier(int step, int nblocks) {
    __syncthreads();
    if (threadIdx.x == 0) {
        __threadfence();                       // drain REDs / prior writes
        atomicAdd(&g_state[2 * MAX_NODES], 1);
        volatile int* p = &g_state[2 * MAX_NODES];
        while (*p < step * nblocks) { }
        __threadfence();                       // acquire
    }
    __syncthreads();
}

__global__ void __launch_bounds__(TPB, 8) fused_kernel(
    const int* __restrict__ dst_ui, const int* __restrict__ dst_iu,
    float* __restrict__ out, int E, int Nn, int nblocks)
{
    const int tid      = blockIdx.x * TPB + threadIdx.x;
    const int nthreads = nblocks * TPB;
    const int e4       = E >> 2;              // full int4 chunks

    // ── Phase 1: in-degree histograms (both relations) ──
    for (int i = tid; i < e4; i += nthreads) {
        int4 a = __ldg((const int4*)dst_ui + i);
        atomicAdd(&g_state[a.x], 1);
        atomicAdd(&g_state[a.y], 1);
        atomicAdd(&g_state[a.z], 1);
        atomicAdd(&g_state[a.w], 1);
        int4 b = __ldg((const int4*)dst_iu + i);
        atomicAdd(&g_state[MAX_NODES + b.x], 1);
        atomicAdd(&g_state[MAX_NODES + b.y], 1);
        atomicAdd(&g_state[MAX_NODES + b.z], 1);
        atomicAdd(&g_state[MAX_NODES + b.w], 1);
    }
    for (int j = (e4 << 2) + tid; j < E; j += nthreads) {
        atomicAdd(&g_state[dst_ui[j]], 1);
        atomicAdd(&g_state[MAX_NODES + dst_iu[j]], 1);
    }
    grid_barrier(1, nblocks);

    // ── Phase 2: per-node reciprocal (precise division == reference) ──
    for (int i = tid; i < Nn; i += nthreads) {
        int cu = g_state[i];
        int ci = g_state[MAX_NODES + i];
        g_rcp[i]             = 1.0f / (float)(cu > 0 ? cu : 1);
        g_rcp[MAX_NODES + i] = 1.0f / (float)(ci > 0 ? ci : 1);
    }
    grid_barrier(2, nblocks);

    // ── Phase 3: per-edge gather ──
    for (int i = tid; i < e4; i += nthreads) {
        int4 a = __ldg((const int4*)dst_ui + i);
        float4 ra;
        ra.x = g_rcp[a.x]; ra.y = g_rcp[a.y];
        ra.z = g_rcp[a.z]; ra.w = g_rcp[a.w];
        ((float4*)out)[i] = ra;

        int4 b = __ldg((const int4*)dst_iu + i);
        float4 rb;
        rb.x = g_rcp[MAX_NODES + b.x]; rb.y = g_rcp[MAX_NODES + b.y];
        rb.z = g_rcp[MAX_NODES + b.z]; rb.w = g_rcp[MAX_NODES + b.w];
        ((float4*)(out + E))[i] = rb;
    }
    for (int j = (e4 << 2) + tid; j < E; j += nthreads) {
        out[j]     = g_rcp[dst_ui[j]];
        out[E + j] = g_rcp[MAX_NODES + dst_iu[j]];
    }
}

extern "C" void kernel_launch(void* const* d_in, const int* in_sizes, int n_in,
                              void* d_out, int out_size) {
    // Inputs: h_user, h_item, Wl_user, bl_user, Wl_item, bl_item,
    //         Wr_user, br_user, Wr_item, br_item, attn_w,
    //         src_ui, dst_ui, src_iu, dst_iu
    const int* dst_ui = (const int*)d_in[12];
    const int* dst_iu = (const int*)d_in[14];
    float* out = (float*)d_out;

    int D  = in_sizes[3];
    int Nn = in_sizes[0] / D;
    if (Nn > MAX_NODES) Nn = MAX_NODES;
    int E = in_sizes[12];

    void* p_state = nullptr;
    cudaGetSymbolAddress(&p_state, g_state);
    cudaMemsetAsync(p_state, 0, (size_t)(2 * MAX_NODES + 32) * sizeof(int));

    int sm = 148;
    cudaDeviceGetAttribute(&sm, cudaDevAttrMultiProcessorCount, 0);
    int nblocks = sm * 4;   // launch_bounds guarantees >=8 resident/SM

    fused_kernel<<<nblocks, TPB>>>(dst_ui, dst_iu, out, E, Nn, nblocks);
}

// round 4
// speedup vs baseline: 1.2897x; 1.2897x over previous
#include <cuda_runtime.h>

// TypeAttention reduces algebraically to alpha[e] = 1 / in_degree(dst[e]) per
// relation (all edges into a dst carry an identical logit -> the per-dst edge
// softmax is uniform = 1/count). Output = concat over the two relations.
//
// 3 graph nodes, no memsets: hist (REDs) -> recip (+self-reset of counts, so
// each replay starts zeroed) -> gather. Static init zeros cover call #1.

#define MAX_NODES 100000
#define TPB 256

// [0, MAX_NODES): cnt_ui ; [MAX_NODES, 2*MAX_NODES): cnt_iu
__device__ int   g_cnt[2 * MAX_NODES];       // zero-initialized at load
__device__ float g_rcp[2 * MAX_NODES];       // fully overwritten each run

__global__ void hist_kernel(const int* __restrict__ dst_ui,
                            const int* __restrict__ dst_iu, int E) {
    int i = blockIdx.x * TPB + threadIdx.x;
    int e4 = E >> 2;
    if (i < e4) {
        int4 a = __ldg((const int4*)dst_ui + i);
        atomicAdd(&g_cnt[a.x], 1);
        atomicAdd(&g_cnt[a.y], 1);
        atomicAdd(&g_cnt[a.z], 1);
        atomicAdd(&g_cnt[a.w], 1);
        int4 b = __ldg((const int4*)dst_iu + i);
        atomicAdd(&g_cnt[MAX_NODES + b.x], 1);
        atomicAdd(&g_cnt[MAX_NODES + b.y], 1);
        atomicAdd(&g_cnt[MAX_NODES + b.z], 1);
        atomicAdd(&g_cnt[MAX_NODES + b.w], 1);
    } else if (i == e4) {
        for (int j = e4 << 2; j < E; j++) {
            atomicAdd(&g_cnt[dst_ui[j]], 1);
            atomicAdd(&g_cnt[MAX_NODES + dst_iu[j]], 1);
        }
    }
}

__global__ void recip_reset_kernel(int Nn) {
    int i = blockIdx.x * TPB + threadIdx.x;
    if (i < Nn) {
        int cu = g_cnt[i];
        int ci = g_cnt[MAX_NODES + i];
        // Precise fp32 division: matches reference's ex/denom exactly.
        g_rcp[i]             = 1.0f / (float)(cu > 0 ? cu : 1);
        g_rcp[MAX_NODES + i] = 1.0f / (float)(ci > 0 ? ci : 1);
        // Self-clean so the next graph replay starts from zeroed counts.
        g_cnt[i]             = 0;
        g_cnt[MAX_NODES + i] = 0;
    }
}

__global__ void gather_kernel(const int* __restrict__ dst_ui,
                              const int* __restrict__ dst_iu,
                              float* __restrict__ out, int E) {
    int i = blockIdx.x * TPB + threadIdx.x;
    int e4 = E >> 2;
    if (i < e4) {
        int4 a = __ldg((const int4*)dst_ui + i);
        float4 ra;
        ra.x = g_rcp[a.x]; ra.y = g_rcp[a.y];
        ra.z = g_rcp[a.z]; ra.w = g_rcp[a.w];
        ((float4*)out)[i] = ra;

        int4 b = __ldg((const int4*)dst_iu + i);
        float4 rb;
        rb.x = g_rcp[MAX_NODES + b.x]; rb.y = g_rcp[MAX_NODES + b.y];
        rb.z = g_rcp[MAX_NODES + b.z]; rb.w = g_rcp[MAX_NODES + b.w];
        ((float4*)(out + E))[i] = rb;
    } else if (i == e4) {
        for (int j = e4 << 2; j < E; j++) {
            out[j]     = g_rcp[dst_ui[j]];
            out[E + j] = g_rcp[MAX_NODES + dst_iu[j]];
        }
    }
}

extern "C" void kernel_launch(void* const* d_in, const int* in_sizes, int n_in,
                              void* d_out, int out_size) {
    // Inputs: h_user, h_item, Wl_user, bl_user, Wl_item, bl_item,
    //         Wr_user, br_user, Wr_item, br_item, attn_w,
    //         src_ui, dst_ui, src_iu, dst_iu
    const int* dst_ui = (const int*)d_in[12];
    const int* dst_iu = (const int*)d_in[14];
    float* out = (float*)d_out;

    int D  = in_sizes[3];
    int Nn = in_sizes[0] / D;
    if (Nn > MAX_NODES) Nn = MAX_NODES;
    int E = in_sizes[12];

    int e4_threads = (E >> 2) + 1;   // +1 thread handles the tail
    int eb = (e4_threads + TPB - 1) / TPB;
    int nb = (Nn + TPB - 1) / TPB;

    hist_kernel<<<eb, TPB>>>(dst_ui, dst_iu, E);
    recip_reset_kernel<<<nb, TPB>>>(Nn);
    gather_kernel<<<eb, TPB>>>(dst_ui, dst_iu, out, E);
}

// round 6
// speedup vs baseline: 1.3549x; 1.0505x over previous
#include <cuda_runtime.h>

// TypeAttention reduces algebraically to alpha[e] = 1 / in_degree(dst[e]) per
// relation: every edge into a given dst carries the identical logit, so the
// per-dst edge softmax is uniform = 1/count. Output = concat over relations.
//
// 3 graph nodes: hist (REDs) -> gather (random count loads + precise per-edge
// division; division cost is ~1us chip-wide) -> memset counts to zero for the
// next graph replay. Static zero-init covers the very first call.

#define MAX_NODES 100000
#define TPB 256

// [0, MAX_NODES): cnt_ui ; [MAX_NODES, 2*MAX_NODES): cnt_iu
__device__ int g_cnt[2 * MAX_NODES];   // zero-initialized at load; re-zeroed
                                       // by the trailing memset each run

__global__ void hist_kernel(const int* __restrict__ dst_ui,
                            const int* __restrict__ dst_iu, int E) {
    int i = blockIdx.x * TPB + threadIdx.x;
    int e4 = E >> 2;
    if (i < e4) {
        int4 a = __ldg((const int4*)dst_ui + i);
        atomicAdd(&g_cnt[a.x], 1);
        atomicAdd(&g_cnt[a.y], 1);
        atomicAdd(&g_cnt[a.z], 1);
        atomicAdd(&g_cnt[a.w], 1);
        int4 b = __ldg((const int4*)dst_iu + i);
        atomicAdd(&g_cnt[MAX_NODES + b.x], 1);
        atomicAdd(&g_cnt[MAX_NODES + b.y], 1);
        atomicAdd(&g_cnt[MAX_NODES + b.z], 1);
        atomicAdd(&g_cnt[MAX_NODES + b.w], 1);
    } else if (i == e4) {
        for (int j = e4 << 2; j < E; j++) {
            atomicAdd(&g_cnt[dst_ui[j]], 1);
            atomicAdd(&g_cnt[MAX_NODES + dst_iu[j]], 1);
        }
    }
}

__global__ void gather_kernel(const int* __restrict__ dst_ui,
                              const int* __restrict__ dst_iu,
                              float* __restrict__ out, int E) {
    int i = blockIdx.x * TPB + threadIdx.x;
    int e4 = E >> 2;
    if (i < e4) {
        int4 a = __ldg((const int4*)dst_ui + i);
        float4 ra;
        ra.x = 1.0f / (float)g_cnt[a.x];
        ra.y = 1.0f / (float)g_cnt[a.y];
        ra.z = 1.0f / (float)g_cnt[a.z];
        ra.w = 1.0f / (float)g_cnt[a.w];
        ((float4*)out)[i] = ra;

        int4 b = __ldg((const int4*)dst_iu + i);
        float4 rb;
        rb.x = 1.0f / (float)g_cnt[MAX_NODES + b.x];
        rb.y = 1.0f / (float)g_cnt[MAX_NODES + b.y];
        rb.z = 1.0f / (float)g_cnt[MAX_NODES + b.z];
        rb.w = 1.0f / (float)g_cnt[MAX_NODES + b.w];
        ((float4*)(out + E))[i] = rb;
    } else if (i == e4) {
        for (int j = e4 << 2; j < E; j++) {
            out[j]     = 1.0f / (float)g_cnt[dst_ui[j]];
            out[E + j] = 1.0f / (float)g_cnt[MAX_NODES + dst_iu[j]];
        }
    }
}

extern "C" void kernel_launch(void* const* d_in, const int* in_sizes, int n_in,
                              void* d_out, int out_size) {
    // Inputs: h_user, h_item, Wl_user, bl_user, Wl_item, bl_item,
    //         Wr_user, br_user, Wr_item, br_item, attn_w,
    //         src_ui, dst_ui, src_iu, dst_iu
    const int* dst_ui = (const int*)d_in[12];
    const int* dst_iu = (const int*)d_in[14];
    float* out = (float*)d_out;

    int E = in_sizes[12];

    int e4_threads = (E >> 2) + 1;   // +1 thread for the tail
    int eb = (e4_threads + TPB - 1) / TPB;

    hist_kernel<<<eb, TPB>>>(dst_ui, dst_iu, E);
    gather_kernel<<<eb, TPB>>>(dst_ui, dst_iu, out, E);

    // Self-clean AFTER consumption so the next replay starts zeroed.
    static void* p_cnt = nullptr;
    if (!p_cnt) cudaGetSymbolAddress(&p_cnt, g_cnt);
    cudaMemsetAsync(p_cnt, 0, sizeof(int) * 2 * MAX_NODES);
}

// round 7
// speedup vs baseline: 1.3792x; 1.0179x over previous
#include <cuda_runtime.h>

// TypeAttention reduces algebraically to alpha[e] = 1 / in_degree(dst[e]) per
// relation (per-dst softmax over identical logits = uniform). Output = concat.
//
// The two relations are independent chains with different bottlenecks per
// phase (hist: L2 atomics; gather: L1tex wavefronts). Fork the graph:
//   s0: hist_ui -> gather_ui --------------\
//   s1:   (after hist_ui) hist_iu -> gather_iu -> join -> memset(counts)
// so gather_ui overlaps hist_iu. Counts are re-zeroed at the end of each
// replay; static zero-init covers the first call.

#define MAX_NODES 100000
#define TPB 256

__device__ int g_cnt[2 * MAX_NODES];   // [0,N): ui  [N,2N): iu

__global__ void hist1_kernel(const int* __restrict__ dst, int* __restrict__ cnt,
                             int E) {
    int i = blockIdx.x * TPB + threadIdx.x;
    int e4 = E >> 2;
    if (i < e4) {
        int4 a = __ldg((const int4*)dst + i);
        atomicAdd(&cnt[a.x], 1);
        atomicAdd(&cnt[a.y], 1);
        atomicAdd(&cnt[a.z], 1);
        atomicAdd(&cnt[a.w], 1);
    } else if (i == e4) {
        for (int j = e4 << 2; j < E; j++) atomicAdd(&cnt[dst[j]], 1);
    }
}

__global__ void gather1_kernel(const int* __restrict__ dst,
                               const int* __restrict__ cnt,
                               float* __restrict__ out, int E) {
    int i = blockIdx.x * TPB + threadIdx.x;
    int e4 = E >> 2;
    if (i < e4) {
        int4 a = __ldg((const int4*)dst + i);
        float4 r;
        r.x = 1.0f / (float)cnt[a.x];
        r.y = 1.0f / (float)cnt[a.y];
        r.z = 1.0f / (float)cnt[a.z];
        r.w = 1.0f / (float)cnt[a.w];
        ((float4*)out)[i] = r;
    } else if (i == e4) {
        for (int j = e4 << 2; j < E; j++) out[j] = 1.0f / (float)cnt[dst[j]];
    }
}

extern "C" void kernel_launch(void* const* d_in, const int* in_sizes, int n_in,
                              void* d_out, int out_size) {
    // Inputs: h_user, h_item, Wl_user, bl_user, Wl_item, bl_item,
    //         Wr_user, br_user, Wr_item, br_item, attn_w,
    //         src_ui, dst_ui, src_iu, dst_iu
    const int* dst_ui = (const int*)d_in[12];
    const int* dst_iu = (const int*)d_in[14];
    float* out = (float*)d_out;
    int E = in_sizes[12];

    static cudaStream_t s1 = nullptr;
    static cudaEvent_t ev_fork = nullptr, ev_join = nullptr;
    static int* p_cnt = nullptr;
    if (!s1) {
        cudaStreamCreateWithFlags(&s1, cudaStreamNonBlocking);
        cudaEventCreateWithFlags(&ev_fork, cudaEventDisableTiming);
        cudaEventCreateWithFlags(&ev_join, cudaEventDisableTiming);
        cudaGetSymbolAddress((void**)&p_cnt, g_cnt);
    }

    int e4_threads = (E >> 2) + 1;
    int eb = (e4_threads + TPB - 1) / TPB;

    int* cnt_ui = p_cnt;
    int* cnt_iu = p_cnt + MAX_NODES;

    // s0 (capture stream): hist_ui
    hist1_kernel<<<eb, TPB>>>(dst_ui, cnt_ui, E);
    cudaEventRecord(ev_fork, 0);

    // s1: hist_iu (starts after hist_ui, overlaps gather_ui) -> gather_iu
    cudaStreamWaitEvent(s1, ev_fork, 0);
    hist1_kernel<<<eb, TPB, 0, s1>>>(dst_iu, cnt_iu, E);

    // s0: gather_ui overlaps hist_iu on s1
    gather1_kernel<<<eb, TPB>>>(dst_ui, cnt_ui, out, E);

    gather1_kernel<<<eb, TPB, 0, s1>>>(dst_iu, cnt_iu, out + E, E);
    cudaEventRecord(ev_join, s1);

    // join, then self-clean counts for the next replay
    cudaStreamWaitEvent(0, ev_join, 0);
    cudaMemsetAsync(p_cnt, 0, sizeof(int) * 2 * MAX_NODES);
}